// round 1
// baseline (speedup 1.0000x reference)
#include <cuda_runtime.h>
#include <float.h>

#define MAXN 32768
#define MAXG 2048
#define TILE 128
#define PITCH 132   // 128 + 4 pad, keeps float4 rows 16B-aligned, conflict-free

// Scratch (no allocations allowed -> __device__ globals)
__device__ float g_h[MAXN * 64];     // node embeddings (8 MB, L2-resident)
__device__ float g_t[MAXG * 64];     // per (graph, feature): max + log(sum exp)
__device__ int   g_seg[MAXG + 1];    // segment starts in sorted batch_hyper

// ---------------------------------------------------------------------------
// Kernel 1: node MLP  h = ( [x || u[batch]] @W1+b1 relu @W2+b2 relu ) @W3+b3
// One thread per node, weights in SMEM (W2 transposed for vectorized reads).
// ---------------------------------------------------------------------------
__global__ __launch_bounds__(128)
void k_node_mlp(const float* __restrict__ x, const float* __restrict__ u,
                const int* __restrict__ batch, int N,
                const float* __restrict__ W1, const float* __restrict__ b1,
                const float* __restrict__ W2, const float* __restrict__ b2,
                const float* __restrict__ W3, const float* __restrict__ b3)
{
    __shared__ float sW1[640], sW2t[4096], sW3[4096], sb1[64], sb2[64], sb3[64];
    int tid = threadIdx.x;
    for (int i = tid; i < 640; i += 128) sW1[i] = W1[i];
    for (int i = tid; i < 4096; i += 128) {
        int m = i >> 6, k = i & 63;
        sW2t[k * 64 + m] = W2[i];          // transpose W2 -> [k][m]
        sW3[i] = W3[i];
    }
    if (tid < 64) { sb1[tid] = b1[tid]; sb2[tid] = b2[tid]; sb3[tid] = b3[tid]; }
    __syncthreads();

    int n = blockIdx.x * 128 + tid;
    if (n >= N) return;

    float in[10];
#pragma unroll
    for (int k = 0; k < 6; k++) in[k] = x[n * 6 + k];
    int g = batch[n];
#pragma unroll
    for (int k = 0; k < 4; k++) in[6 + k] = u[g * 4 + k];

    float h1[64];
#pragma unroll
    for (int j = 0; j < 64; j++) h1[j] = sb1[j];
#pragma unroll
    for (int k = 0; k < 10; k++) {
        float v = in[k];
#pragma unroll
        for (int j = 0; j < 64; j += 4) {
            float4 w = *(const float4*)&sW1[k * 64 + j];
            h1[j]   = fmaf(v, w.x, h1[j]);   h1[j+1] = fmaf(v, w.y, h1[j+1]);
            h1[j+2] = fmaf(v, w.z, h1[j+2]); h1[j+3] = fmaf(v, w.w, h1[j+3]);
        }
    }
#pragma unroll
    for (int j = 0; j < 64; j++) h1[j] = fmaxf(h1[j], 0.f);

    // Fuse layer2 + layer3: produce h2[k] on the fly, accumulate into acc[64].
    float acc[64];
#pragma unroll
    for (int j = 0; j < 64; j++) acc[j] = sb3[j];
    for (int k = 0; k < 64; k++) {
        float hv0 = sb2[k], hv1 = 0.f, hv2 = 0.f, hv3 = 0.f;
#pragma unroll
        for (int m = 0; m < 64; m += 4) {
            float4 w = *(const float4*)&sW2t[k * 64 + m];
            hv0 = fmaf(h1[m],   w.x, hv0); hv1 = fmaf(h1[m+1], w.y, hv1);
            hv2 = fmaf(h1[m+2], w.z, hv2); hv3 = fmaf(h1[m+3], w.w, hv3);
        }
        float hv = fmaxf(hv0 + hv1 + hv2 + hv3, 0.f);
#pragma unroll
        for (int j = 0; j < 64; j += 4) {
            float4 w = *(const float4*)&sW3[k * 64 + j];
            acc[j]   = fmaf(hv, w.x, acc[j]);   acc[j+1] = fmaf(hv, w.y, acc[j+1]);
            acc[j+2] = fmaf(hv, w.z, acc[j+2]); acc[j+3] = fmaf(hv, w.w, acc[j+3]);
        }
    }
#pragma unroll
    for (int j = 0; j < 64; j += 4)
        *(float4*)&g_h[n * 64 + j] = make_float4(acc[j], acc[j+1], acc[j+2], acc[j+3]);
}

// ---------------------------------------------------------------------------
// Kernel 2: segment starts from sorted batch_hyper
// ---------------------------------------------------------------------------
__global__ void k_seg(const int* __restrict__ bh, int E, int G)
{
    int e = blockIdx.x * blockDim.x + threadIdx.x;
    if (e >= E) return;
    int cur = bh[e];
    if (e == 0) { for (int g = 0; g <= cur; g++) g_seg[g] = 0; }
    else { int prev = bh[e - 1]; for (int g = prev + 1; g <= cur; g++) g_seg[g] = e; }
    if (e == E - 1) { for (int g = cur + 1; g <= G; g++) g_seg[g] = E; }
}

// ---------------------------------------------------------------------------
// Kernel 3: per-(graph, feature) online softmax stats: t = max + log(sum exp)
// Block per graph; 64 feature lanes x 4 edge-strided partials.
// ---------------------------------------------------------------------------
__global__ __launch_bounds__(256)
void k_stats(const int* __restrict__ hei, int E, int R)
{
    int g = blockIdx.x;
    int s0 = g_seg[g], s1 = g_seg[g + 1];
    int f = threadIdx.x & 63, sub = threadIdx.x >> 6;

    float m = -FLT_MAX, s = 0.f;
    for (int e = s0 + sub; e < s1; e += 4) {
        float xh = 0.f;
        for (int ri = 0; ri < R; ri++) {
            int idx = hei[ri * E + e];
            xh += g_h[idx * 64 + f];
        }
        if (xh > m) { s = s * __expf(m - xh) + 1.f; m = xh; }
        else        { s += __expf(xh - m); }
    }
    __shared__ float sm[4][64], ss[4][64];
    sm[sub][f] = m; ss[sub][f] = s;
    __syncthreads();
    if (sub == 0) {
        float M = sm[0][f];
#pragma unroll
        for (int k = 1; k < 4; k++) M = fmaxf(M, sm[k][f]);
        float S = 0.f;
#pragma unroll
        for (int k = 0; k < 4; k++) S += ss[k][f] * __expf(sm[k][f] - M);
        g_t[g * 64 + f] = M + __logf(S);   // coef = exp(xh - t)
    }
}

// ---------------------------------------------------------------------------
// Kernel 4: fully fused per-edge pipeline. 128 edges/CTA, 512 threads,
// weights persistent in SMEM, activations staged transposed [feat][edge].
// 4x4 register-blocked GEMM micro-kernel (2 x LDS.128 per 16 FFMA).
// ---------------------------------------------------------------------------
__device__ __forceinline__ void mma_step(const float* __restrict__ A, int apitch,
                                         const float* __restrict__ W,
                                         int k, int e0, int j0, float acc[4][4])
{
    float4 a = *(const float4*)&A[k * apitch + e0];
    float4 w = *(const float4*)&W[k * 64 + j0];
    float av[4] = {a.x, a.y, a.z, a.w};
    float wv[4] = {w.x, w.y, w.z, w.w};
#pragma unroll
    for (int i = 0; i < 4; i++)
#pragma unroll
        for (int jj = 0; jj < 4; jj++) acc[i][jj] = fmaf(av[i], wv[jj], acc[i][jj]);
}

__global__ __launch_bounds__(512)
void k_fused(const int* __restrict__ hei, const int* __restrict__ bh,
             int E, int R,
             const float* __restrict__ Wt,
             const float* __restrict__ V1, const float* __restrict__ c1,
             const float* __restrict__ V2, const float* __restrict__ c2,
             const float* __restrict__ V3, const float* __restrict__ c3,
             float* __restrict__ out, int write_bh)
{
    extern __shared__ float smem[];
    float* sWt = smem;                    // 4096
    float* sV1 = sWt + 4096;              // 8192
    float* sV2 = sV1 + 8192;              // 4096
    float* sV3 = sV2 + 4096;              // 64
    float* sc1 = sV3 + 64;                // 64
    float* sc2 = sc1 + 64;                // 64
    float* sT0 = sc2 + 64;                // 64*PITCH  x_hyper^T
    float* sT1 = sT0 + 64 * PITCH;        // x_hyper_hat^T
    float* sT2 = sT1 + 64 * PITCH;        // A^T
    __shared__ int sG[TILE];

    int tid = threadIdx.x;
    for (int i = tid; i < 4096; i += 512) { sWt[i] = Wt[i]; sV2[i] = V2[i]; }
    for (int i = tid; i < 8192; i += 512) sV1[i] = V1[i];
    if (tid < 64) { sV3[tid] = V3[tid]; sc1[tid] = c1[tid]; sc2[tid] = c2[tid]; }

    // ---- gather x_hyper (transposed into SMEM) ----
    int base = blockIdx.x * TILE;
    int el = tid & 127, fq = tid >> 7;         // edge-local, feature quarter
    int e = base + el; if (e >= E) e = E - 1;  // clamp (padding lanes harmless)
    if (fq == 0) sG[el] = bh[e];
    {
        int f0 = fq * 16;
        float xa[16];
#pragma unroll
        for (int ff = 0; ff < 16; ff++) xa[ff] = 0.f;
        for (int ri = 0; ri < R; ri++) {
            int idx = hei[ri * E + e];
            const float4* hp = (const float4*)&g_h[idx * 64 + f0];
#pragma unroll
            for (int q = 0; q < 4; q++) {
                float4 v = hp[q];
                xa[q*4+0] += v.x; xa[q*4+1] += v.y; xa[q*4+2] += v.z; xa[q*4+3] += v.w;
            }
        }
#pragma unroll
        for (int ff = 0; ff < 16; ff++) sT0[(f0 + ff) * PITCH + el] = xa[ff];
    }
    __syncthreads();

    int te = tid & 31, tf = tid >> 5;
    int e0 = te * 4, j0 = tf * 4;
    float acc[4][4];

    // ---- GEMM 1: x_hyper_hat = coef * relu(x_hyper @ weight) ----
#pragma unroll
    for (int i = 0; i < 4; i++)
#pragma unroll
        for (int jj = 0; jj < 4; jj++) acc[i][jj] = 0.f;
#pragma unroll 16
    for (int k = 0; k < 64; k++) mma_step(sT0, PITCH, sWt, k, e0, j0, acc);

    int gi[4];
#pragma unroll
    for (int i = 0; i < 4; i++) gi[i] = sG[e0 + i];
#pragma unroll
    for (int jj = 0; jj < 4; jj++) {
        int j = j0 + jj;
        float4 x4 = *(const float4*)&sT0[j * PITCH + e0];
        float r0 = fmaxf(acc[0][jj], 0.f) * __expf(x4.x - g_t[gi[0] * 64 + j]);
        float r1 = fmaxf(acc[1][jj], 0.f) * __expf(x4.y - g_t[gi[1] * 64 + j]);
        float r2 = fmaxf(acc[2][jj], 0.f) * __expf(x4.z - g_t[gi[2] * 64 + j]);
        float r3 = fmaxf(acc[3][jj], 0.f) * __expf(x4.w - g_t[gi[3] * 64 + j]);
        *(float4*)&sT1[j * PITCH + e0] = make_float4(r0, r1, r2, r3);
    }
    __syncthreads();

    // ---- GEMM 2: A = relu([x_hyper || x_hyper_hat] @ V1 + c1)  (K = 128) ----
#pragma unroll
    for (int i = 0; i < 4; i++)
#pragma unroll
        for (int jj = 0; jj < 4; jj++) acc[i][jj] = 0.f;
#pragma unroll 16
    for (int k = 0; k < 64; k++) mma_step(sT0, PITCH, sV1, k, e0, j0, acc);
#pragma unroll 16
    for (int k = 0; k < 64; k++) mma_step(sT1, PITCH, sV1 + 64 * 64, k, e0, j0, acc);
#pragma unroll
    for (int jj = 0; jj < 4; jj++) {
        int j = j0 + jj;
        float bb = sc1[j];
        float4 r = make_float4(fmaxf(acc[0][jj] + bb, 0.f), fmaxf(acc[1][jj] + bb, 0.f),
                               fmaxf(acc[2][jj] + bb, 0.f), fmaxf(acc[3][jj] + bb, 0.f));
        *(float4*)&sT2[j * PITCH + e0] = r;
    }
    __syncthreads();

    // ---- GEMM 3: B = relu(A @ V2 + c2) -> reuse sT0 ----
#pragma unroll
    for (int i = 0; i < 4; i++)
#pragma unroll
        for (int jj = 0; jj < 4; jj++) acc[i][jj] = 0.f;
#pragma unroll 16
    for (int k = 0; k < 64; k++) mma_step(sT2, PITCH, sV2, k, e0, j0, acc);
#pragma unroll
    for (int jj = 0; jj < 4; jj++) {
        int j = j0 + jj;
        float bb = sc2[j];
        float4 r = make_float4(fmaxf(acc[0][jj] + bb, 0.f), fmaxf(acc[1][jj] + bb, 0.f),
                               fmaxf(acc[2][jj] + bb, 0.f), fmaxf(acc[3][jj] + bb, 0.f));
        *(float4*)&sT0[j * PITCH + e0] = r;
    }
    __syncthreads();

    // ---- final: logit = B @ V3 + c3, sigmoid ----
    if (tid < TILE) {
        int eo = base + tid;
        float a0 = 0.f, a1 = 0.f;
#pragma unroll 8
        for (int j = 0; j < 64; j += 2) {
            a0 = fmaf(sT0[j * PITCH + tid],       sV3[j],     a0);
            a1 = fmaf(sT0[(j + 1) * PITCH + tid], sV3[j + 1], a1);
        }
        float v = a0 + a1 + c3[0];
        float o = 1.f / (1.f + __expf(-v));
        if (eo < E) out[eo] = o;
    } else if (write_bh && tid < 2 * TILE) {
        int el2 = tid - TILE;
        int eo = base + el2;
        if (eo < E) out[E + eo] = (float)sG[el2];
    }
}

// ---------------------------------------------------------------------------
extern "C" void kernel_launch(void* const* d_in, const int* in_sizes, int n_in,
                              void* d_out, int out_size)
{
    const float* x     = (const float*)d_in[0];
    const float* u     = (const float*)d_in[1];
    const int*   batch = (const int*)d_in[2];
    const int*   hei   = (const int*)d_in[3];
    const int*   bh    = (const int*)d_in[4];

    int N = in_sizes[2];
    int E = in_sizes[4];
    int G = in_sizes[1] / 4;
    int R = in_sizes[3] / E;

    // Weights start after the (possibly present) scalar 'r'. W1 has 10*64=640 elems.
    int wb = 5;
    while (wb < n_in && in_sizes[wb] != 640) wb++;
    const float* W1 = (const float*)d_in[wb + 0];
    const float* b1 = (const float*)d_in[wb + 1];
    const float* W2 = (const float*)d_in[wb + 2];
    const float* b2 = (const float*)d_in[wb + 3];
    const float* W3 = (const float*)d_in[wb + 4];
    const float* b3 = (const float*)d_in[wb + 5];
    const float* Wt = (const float*)d_in[wb + 6];
    const float* V1 = (const float*)d_in[wb + 7];
    const float* c1 = (const float*)d_in[wb + 8];
    const float* V2 = (const float*)d_in[wb + 9];
    const float* c2 = (const float*)d_in[wb + 10];
    const float* V3 = (const float*)d_in[wb + 11];
    const float* c3 = (const float*)d_in[wb + 12];

    float* out = (float*)d_out;
    int write_bh = (out_size >= 2 * E) ? 1 : 0;

    k_node_mlp<<<(N + 127) / 128, 128>>>(x, u, batch, N, W1, b1, W2, b2, W3, b3);
    k_seg<<<(E + 255) / 256, 256>>>(bh, E, G);
    k_stats<<<G, 256>>>(hei, E, R);

    size_t shbytes = (size_t)(16576 + 3 * 64 * PITCH) * sizeof(float);  // ~167.7 KB
    cudaFuncSetAttribute(k_fused, cudaFuncAttributeMaxDynamicSharedMemorySize, (int)shbytes);
    k_fused<<<(E + TILE - 1) / TILE, 512, shbytes>>>(hei, bh, E, R, Wt, V1, c1, V2, c2,
                                                     V3, c3, out, write_bh);
}

// round 2
// speedup vs baseline: 1.1584x; 1.1584x over previous
#include <cuda_runtime.h>
#include <float.h>

typedef unsigned long long ull;

#define MAXN 32768
#define MAXG 2048
#define TILE 256
#define PITCHE 256      // [feat][edge] staging pitch (all accesses warp-contiguous)
#define THREADS 256

// Scratch (no allocations allowed -> __device__ globals)
__device__ float g_h[MAXN * 64];     // node embeddings (8 MB, L2-resident)
__device__ float g_t[MAXG * 64];     // per (graph, feature): max + log(sum exp)
__device__ int   g_seg[MAXG + 1];    // segment starts in sorted batch_hyper

// ---- f32x2 packed helpers (sm_103a FFMA2 path) ------------------------------
__device__ __forceinline__ ull pk2(float lo, float hi) {
    ull r;
    asm("mov.b64 %0, {%1, %2};" : "=l"(r) : "r"(__float_as_uint(lo)), "r"(__float_as_uint(hi)));
    return r;
}
__device__ __forceinline__ void upk2(ull v, float& lo, float& hi) {
    unsigned a, b;
    asm("mov.b64 {%0, %1}, %2;" : "=r"(a), "=r"(b) : "l"(v));
    lo = __uint_as_float(a); hi = __uint_as_float(b);
}
__device__ __forceinline__ ull ffma2(ull a, ull b, ull c) {
    ull d;
    asm("fma.rn.f32x2 %0, %1, %2, %3;" : "=l"(d) : "l"(a), "l"(b), "l"(c));
    return d;
}

// ---------------------------------------------------------------------------
// Kernel 1: node MLP  h = ( [x || u[batch]] @W1+b1 relu @W2+b2 relu ) @W3+b3
// ---------------------------------------------------------------------------
__global__ __launch_bounds__(128)
void k_node_mlp(const float* __restrict__ x, const float* __restrict__ u,
                const int* __restrict__ batch, int N,
                const float* __restrict__ W1, const float* __restrict__ b1,
                const float* __restrict__ W2, const float* __restrict__ b2,
                const float* __restrict__ W3, const float* __restrict__ b3)
{
    __shared__ float sW1[640], sW2t[4096], sW3[4096], sb1[64], sb2[64], sb3[64];
    int tid = threadIdx.x;
    for (int i = tid; i < 640; i += 128) sW1[i] = W1[i];
    for (int i = tid; i < 4096; i += 128) {
        int m = i >> 6, k = i & 63;
        sW2t[k * 64 + m] = W2[i];
        sW3[i] = W3[i];
    }
    if (tid < 64) { sb1[tid] = b1[tid]; sb2[tid] = b2[tid]; sb3[tid] = b3[tid]; }
    __syncthreads();

    int n = blockIdx.x * 128 + tid;
    if (n >= N) return;

    float in[10];
#pragma unroll
    for (int k = 0; k < 6; k++) in[k] = x[n * 6 + k];
    int g = batch[n];
#pragma unroll
    for (int k = 0; k < 4; k++) in[6 + k] = u[g * 4 + k];

    float h1[64];
#pragma unroll
    for (int j = 0; j < 64; j++) h1[j] = sb1[j];
#pragma unroll
    for (int k = 0; k < 10; k++) {
        float v = in[k];
#pragma unroll
        for (int j = 0; j < 64; j += 4) {
            float4 w = *(const float4*)&sW1[k * 64 + j];
            h1[j]   = fmaf(v, w.x, h1[j]);   h1[j+1] = fmaf(v, w.y, h1[j+1]);
            h1[j+2] = fmaf(v, w.z, h1[j+2]); h1[j+3] = fmaf(v, w.w, h1[j+3]);
        }
    }
#pragma unroll
    for (int j = 0; j < 64; j++) h1[j] = fmaxf(h1[j], 0.f);

    float acc[64];
#pragma unroll
    for (int j = 0; j < 64; j++) acc[j] = sb3[j];
    for (int k = 0; k < 64; k++) {
        float hv0 = sb2[k], hv1 = 0.f, hv2 = 0.f, hv3 = 0.f;
#pragma unroll
        for (int m = 0; m < 64; m += 4) {
            float4 w = *(const float4*)&sW2t[k * 64 + m];
            hv0 = fmaf(h1[m],   w.x, hv0); hv1 = fmaf(h1[m+1], w.y, hv1);
            hv2 = fmaf(h1[m+2], w.z, hv2); hv3 = fmaf(h1[m+3], w.w, hv3);
        }
        float hv = fmaxf(hv0 + hv1 + hv2 + hv3, 0.f);
#pragma unroll
        for (int j = 0; j < 64; j += 4) {
            float4 w = *(const float4*)&sW3[k * 64 + j];
            acc[j]   = fmaf(hv, w.x, acc[j]);   acc[j+1] = fmaf(hv, w.y, acc[j+1]);
            acc[j+2] = fmaf(hv, w.z, acc[j+2]); acc[j+3] = fmaf(hv, w.w, acc[j+3]);
        }
    }
#pragma unroll
    for (int j = 0; j < 64; j += 4)
        *(float4*)&g_h[n * 64 + j] = make_float4(acc[j], acc[j+1], acc[j+2], acc[j+3]);
}

// ---------------------------------------------------------------------------
// Kernel 2: segment starts from sorted batch_hyper
// ---------------------------------------------------------------------------
__global__ void k_seg(const int* __restrict__ bh, int E, int G)
{
    int e = blockIdx.x * blockDim.x + threadIdx.x;
    if (e >= E) return;
    int cur = bh[e];
    if (e == 0) { for (int g = 0; g <= cur; g++) g_seg[g] = 0; }
    else { int prev = bh[e - 1]; for (int g = prev + 1; g <= cur; g++) g_seg[g] = e; }
    if (e == E - 1) { for (int g = cur + 1; g <= G; g++) g_seg[g] = E; }
}

// ---------------------------------------------------------------------------
// Kernel 3: per-(graph, feature) softmax stats: t = max + log(sum exp)
// ---------------------------------------------------------------------------
__global__ __launch_bounds__(256)
void k_stats(const int* __restrict__ hei, int E, int R)
{
    int g = blockIdx.x;
    int s0 = g_seg[g], s1 = g_seg[g + 1];
    int f = threadIdx.x & 63, sub = threadIdx.x >> 6;

    float m = -FLT_MAX, s = 0.f;
    for (int e = s0 + sub; e < s1; e += 4) {
        float xh = 0.f;
        for (int ri = 0; ri < R; ri++) {
            int idx = hei[ri * E + e];
            xh += g_h[idx * 64 + f];
        }
        if (xh > m) { s = s * __expf(m - xh) + 1.f; m = xh; }
        else        { s += __expf(xh - m); }
    }
    __shared__ float sm[4][64], ss[4][64];
    sm[sub][f] = m; ss[sub][f] = s;
    __syncthreads();
    if (sub == 0) {
        float M = sm[0][f];
#pragma unroll
        for (int k = 1; k < 4; k++) M = fmaxf(M, sm[k][f]);
        float S = 0.f;
#pragma unroll
        for (int k = 0; k < 4; k++) S += ss[k][f] * __expf(sm[k][f] - M);
        g_t[g * 64 + f] = M + __logf(S);
    }
}

// ---------------------------------------------------------------------------
// Kernel 4: fused per-edge pipeline. 256 edges/CTA, 256 threads.
// 8e x 8j register blocking with packed FFMA2 (f32x2), e interleaved by 64.
// ---------------------------------------------------------------------------
__device__ __forceinline__ void loadA4(const float* __restrict__ A, int k, int te2, ull a[4])
{
#pragma unroll
    for (int i = 0; i < 4; i++)
        a[i] = *(const ull*)&A[k * PITCHE + te2 + 64 * i];
}
__device__ __forceinline__ void loadW8(const float* __restrict__ W, int k, int j0, ull w[8])
{
    float4 w0 = *(const float4*)&W[k * 64 + j0];
    float4 w1 = *(const float4*)&W[k * 64 + j0 + 4];
    w[0] = pk2(w0.x, w0.x); w[1] = pk2(w0.y, w0.y);
    w[2] = pk2(w0.z, w0.z); w[3] = pk2(w0.w, w0.w);
    w[4] = pk2(w1.x, w1.x); w[5] = pk2(w1.y, w1.y);
    w[6] = pk2(w1.z, w1.z); w[7] = pk2(w1.w, w1.w);
}
__device__ __forceinline__ void fmas(const ull a[4], const ull w[8], ull acc[4][8])
{
#pragma unroll
    for (int i = 0; i < 4; i++)
#pragma unroll
        for (int j = 0; j < 8; j++)
            acc[i][j] = ffma2(a[i], w[j], acc[i][j]);
}
// K=64 GEMM slab with manual double-buffering; loop kept rolled (I$).
__device__ __forceinline__ void gemm64(const float* __restrict__ A, const float* __restrict__ W,
                                       int te2, int j0, ull acc[4][8])
{
    ull a0[4], a1[4], w0[8], w1[8];
    loadA4(A, 0, te2, a0); loadW8(W, 0, j0, w0);
#pragma unroll 1
    for (int k = 0; k < 62; k += 2) {
        loadA4(A, k + 1, te2, a1); loadW8(W, k + 1, j0, w1);
        fmas(a0, w0, acc);
        loadA4(A, k + 2, te2, a0); loadW8(W, k + 2, j0, w0);
        fmas(a1, w1, acc);
    }
    loadA4(A, 63, te2, a1); loadW8(W, 63, j0, w1);
    fmas(a0, w0, acc);
    fmas(a1, w1, acc);
}

__global__ __launch_bounds__(THREADS)
void k_fused(const int* __restrict__ hei, const int* __restrict__ bh,
             int E, int R,
             const float* __restrict__ Wt,
             const float* __restrict__ V1, const float* __restrict__ c1,
             const float* __restrict__ V2, const float* __restrict__ c2,
             const float* __restrict__ V3, const float* __restrict__ c3,
             float* __restrict__ out, int write_bh)
{
    extern __shared__ float smem[];
    float* sWt = smem;                    // 4096
    float* sV1 = sWt + 4096;              // 8192
    float* sV2 = sV1 + 8192;              // 4096
    float* sV3 = sV2 + 4096;              // 64
    float* sc1 = sV3 + 64;                // 64
    float* sc2 = sc1 + 64;                // 64
    float* sT0 = sc2 + 64;                // 64*PITCHE
    float* sT1 = sT0 + 64 * PITCHE;       // 64*PITCHE
    __shared__ int sG[TILE];

    int tid = threadIdx.x;
    for (int i = tid; i < 4096; i += THREADS) { sWt[i] = Wt[i]; sV2[i] = V2[i]; }
    for (int i = tid; i < 8192; i += THREADS) sV1[i] = V1[i];
    if (tid < 64) { sV3[tid] = V3[tid]; sc1[tid] = c1[tid]; sc2[tid] = c2[tid]; }

    // ---- gather x_hyper (transposed into sT0), one edge per thread ----
    int base = blockIdx.x * TILE;
    int e = base + tid; if (e >= E) e = E - 1;   // clamp; padded lanes harmless
    sG[tid] = bh[e];
    {
        float xa[64];
        {
            int idx = hei[e];
            const float4* hp = (const float4*)&g_h[idx * 64];
#pragma unroll
            for (int q = 0; q < 16; q++) {
                float4 v = hp[q];
                xa[q*4+0] = v.x; xa[q*4+1] = v.y; xa[q*4+2] = v.z; xa[q*4+3] = v.w;
            }
        }
        for (int ri = 1; ri < R; ri++) {
            int idx = hei[ri * E + e];
            const float4* hp = (const float4*)&g_h[idx * 64];
#pragma unroll
            for (int q = 0; q < 16; q++) {
                float4 v = hp[q];
                xa[q*4+0] += v.x; xa[q*4+1] += v.y; xa[q*4+2] += v.z; xa[q*4+3] += v.w;
            }
        }
#pragma unroll
        for (int f = 0; f < 64; f++) sT0[f * PITCHE + tid] = xa[f];
    }
    __syncthreads();

    int te2 = (tid & 31) * 2;       // base edge (pair) within tile
    int j0  = (tid >> 5) * 8;       // 8 output features
    ull acc[4][8];

    // ---- GEMM 1: x_hyper_hat = coef * relu(x_hyper @ weight) ----
#pragma unroll
    for (int i = 0; i < 4; i++)
#pragma unroll
        for (int j = 0; j < 8; j++) acc[i][j] = 0ULL;
    gemm64(sT0, sWt, te2, j0, acc);

#pragma unroll
    for (int i = 0; i < 4; i++) {
        int ep = te2 + 64 * i;
        const float* t0 = &g_t[sG[ep] * 64];
        const float* t1 = &g_t[sG[ep + 1] * 64];
#pragma unroll
        for (int jj = 0; jj < 8; jj++) {
            int j = j0 + jj;
            float alo, ahi, xlo, xhi;
            upk2(acc[i][jj], alo, ahi);
            upk2(*(const ull*)&sT0[j * PITCHE + ep], xlo, xhi);
            float r0 = fmaxf(alo, 0.f) * __expf(xlo - __ldg(&t0[j]));
            float r1 = fmaxf(ahi, 0.f) * __expf(xhi - __ldg(&t1[j]));
            *(ull*)&sT1[j * PITCHE + ep] = pk2(r0, r1);
        }
    }
    __syncthreads();

    // ---- GEMM 2: A = relu([x_hyper || x_hyper_hat] @ V1 + c1), K=128 ----
#pragma unroll
    for (int i = 0; i < 4; i++)
#pragma unroll
        for (int j = 0; j < 8; j++) acc[i][j] = 0ULL;
    gemm64(sT0, sV1,           te2, j0, acc);
    gemm64(sT1, sV1 + 64 * 64, te2, j0, acc);
#pragma unroll
    for (int jj = 0; jj < 8; jj++) {
        float bb = sc1[j0 + jj];
#pragma unroll
        for (int i = 0; i < 4; i++) {
            float alo, ahi;
            upk2(acc[i][jj], alo, ahi);
            acc[i][jj] = pk2(fmaxf(alo + bb, 0.f), fmaxf(ahi + bb, 0.f));
        }
    }
    __syncthreads();   // all reads of sT0/sT1 done
#pragma unroll
    for (int i = 0; i < 4; i++) {
        int ep = te2 + 64 * i;
#pragma unroll
        for (int jj = 0; jj < 8; jj++)
            *(ull*)&sT0[(j0 + jj) * PITCHE + ep] = acc[i][jj];
    }
    __syncthreads();

    // ---- GEMM 3: B = relu(A @ V2 + c2) ----
#pragma unroll
    for (int i = 0; i < 4; i++)
#pragma unroll
        for (int j = 0; j < 8; j++) acc[i][j] = 0ULL;
    gemm64(sT0, sV2, te2, j0, acc);
#pragma unroll
    for (int jj = 0; jj < 8; jj++) {
        float bb = sc2[j0 + jj];
#pragma unroll
        for (int i = 0; i < 4; i++) {
            float alo, ahi;
            upk2(acc[i][jj], alo, ahi);
            acc[i][jj] = pk2(fmaxf(alo + bb, 0.f), fmaxf(ahi + bb, 0.f));
        }
    }
    __syncthreads();
#pragma unroll
    for (int i = 0; i < 4; i++) {
        int ep = te2 + 64 * i;
#pragma unroll
        for (int jj = 0; jj < 8; jj++)
            *(ull*)&sT1[(j0 + jj) * PITCHE + ep] = acc[i][jj];
    }
    __syncthreads();

    // ---- final: logit = B @ V3 + c3, sigmoid ----
    {
        int eo = base + tid;
        float a0 = 0.f, a1 = 0.f;
#pragma unroll 8
        for (int j = 0; j < 64; j += 2) {
            a0 = fmaf(sT1[j * PITCHE + tid],       sV3[j],     a0);
            a1 = fmaf(sT1[(j + 1) * PITCHE + tid], sV3[j + 1], a1);
        }
        float v = a0 + a1 + c3[0];
        float o = 1.f / (1.f + __expf(-v));
        if (eo < E) {
            out[eo] = o;
            if (write_bh) out[E + eo] = (float)sG[tid];
        }
    }
}

// ---------------------------------------------------------------------------
extern "C" void kernel_launch(void* const* d_in, const int* in_sizes, int n_in,
                              void* d_out, int out_size)
{
    const float* x     = (const float*)d_in[0];
    const float* u     = (const float*)d_in[1];
    const int*   batch = (const int*)d_in[2];
    const int*   hei   = (const int*)d_in[3];
    const int*   bh    = (const int*)d_in[4];

    int N = in_sizes[2];
    int E = in_sizes[4];
    int G = in_sizes[1] / 4;
    int R = in_sizes[3] / E;

    int wb = 5;
    while (wb < n_in && in_sizes[wb] != 640) wb++;
    const float* W1 = (const float*)d_in[wb + 0];
    const float* b1 = (const float*)d_in[wb + 1];
    const float* W2 = (const float*)d_in[wb + 2];
    const float* b2 = (const float*)d_in[wb + 3];
    const float* W3 = (const float*)d_in[wb + 4];
    const float* b3 = (const float*)d_in[wb + 5];
    const float* Wt = (const float*)d_in[wb + 6];
    const float* V1 = (const float*)d_in[wb + 7];
    const float* c1 = (const float*)d_in[wb + 8];
    const float* V2 = (const float*)d_in[wb + 9];
    const float* c2 = (const float*)d_in[wb + 10];
    const float* V3 = (const float*)d_in[wb + 11];
    const float* c3 = (const float*)d_in[wb + 12];

    float* out = (float*)d_out;
    int write_bh = (out_size >= 2 * E) ? 1 : 0;

    k_node_mlp<<<(N + 127) / 128, 128>>>(x, u, batch, N, W1, b1, W2, b2, W3, b3);
    k_seg<<<(E + 255) / 256, 256>>>(bh, E, G);
    k_stats<<<G, 256>>>(hei, E, R);

    size_t shbytes = (size_t)(16576 + 2 * 64 * PITCHE) * sizeof(float);  // ~192.8 KB
    cudaFuncSetAttribute(k_fused, cudaFuncAttributeMaxDynamicSharedMemorySize, (int)shbytes);
    k_fused<<<(E + TILE - 1) / TILE, THREADS, shbytes>>>(hei, bh, E, R, Wt, V1, c1,
                                                         V2, c2, V3, c3, out, write_bh);
}

// round 4
// speedup vs baseline: 2.1595x; 1.8643x over previous
#include <cuda_runtime.h>
#include <float.h>
#include <stdint.h>

#define MAXN 32768
#define MAXG 2048

// Scratch (no allocations allowed -> __device__ globals)
__device__ float g_h[MAXN * 64];     // node embeddings (8 MB, L2-resident)
__device__ float g_t[MAXG * 64];     // per (graph, feature): max + log(sum exp)
__device__ int   g_seg[MAXG + 1];    // segment starts in sorted batch_hyper

static __device__ __forceinline__ float tf32r(float x) {
    uint32_t r; asm("cvt.rna.tf32.f32 %0, %1;" : "=r"(r) : "f"(x));
    return __uint_as_float(r);
}
static __device__ __forceinline__ void mma8(float c[4], uint32_t a0, uint32_t a1,
                                            uint32_t a2, uint32_t a3,
                                            uint32_t b0, uint32_t b1) {
    asm volatile("mma.sync.aligned.m16n8k8.row.col.f32.tf32.tf32.f32 "
                 "{%0,%1,%2,%3}, {%4,%5,%6,%7}, {%8,%9}, {%0,%1,%2,%3};"
                 : "+f"(c[0]), "+f"(c[1]), "+f"(c[2]), "+f"(c[3])
                 : "r"(a0), "r"(a1), "r"(a2), "r"(a3), "r"(b0), "r"(b1));
}

// ---------------------------------------------------------------------------
// Kernel 1: node MLP
// ---------------------------------------------------------------------------
__global__ __launch_bounds__(128)
void k_node_mlp(const float* __restrict__ x, const float* __restrict__ u,
                const int* __restrict__ batch, int N,
                const float* __restrict__ W1, const float* __restrict__ b1,
                const float* __restrict__ W2, const float* __restrict__ b2,
                const float* __restrict__ W3, const float* __restrict__ b3)
{
    __shared__ float sW1[640], sW2t[4096], sW3[4096], sb1[64], sb2[64], sb3[64];
    int tid = threadIdx.x;
    for (int i = tid; i < 640; i += 128) sW1[i] = W1[i];
    for (int i = tid; i < 4096; i += 128) {
        int m = i >> 6, k = i & 63;
        sW2t[k * 64 + m] = W2[i];
        sW3[i] = W3[i];
    }
    if (tid < 64) { sb1[tid] = b1[tid]; sb2[tid] = b2[tid]; sb3[tid] = b3[tid]; }
    __syncthreads();

    int n = blockIdx.x * 128 + tid;
    if (n >= N) return;

    float in[10];
#pragma unroll
    for (int k = 0; k < 6; k++) in[k] = x[n * 6 + k];
    int g = batch[n];
#pragma unroll
    for (int k = 0; k < 4; k++) in[6 + k] = u[g * 4 + k];

    float h1[64];
#pragma unroll
    for (int j = 0; j < 64; j++) h1[j] = sb1[j];
#pragma unroll
    for (int k = 0; k < 10; k++) {
        float v = in[k];
#pragma unroll
        for (int j = 0; j < 64; j += 4) {
            float4 w = *(const float4*)&sW1[k * 64 + j];
            h1[j]   = fmaf(v, w.x, h1[j]);   h1[j+1] = fmaf(v, w.y, h1[j+1]);
            h1[j+2] = fmaf(v, w.z, h1[j+2]); h1[j+3] = fmaf(v, w.w, h1[j+3]);
        }
    }
#pragma unroll
    for (int j = 0; j < 64; j++) h1[j] = fmaxf(h1[j], 0.f);

    float acc[64];
#pragma unroll
    for (int j = 0; j < 64; j++) acc[j] = sb3[j];
    for (int k = 0; k < 64; k++) {
        float hv0 = sb2[k], hv1 = 0.f, hv2 = 0.f, hv3 = 0.f;
#pragma unroll
        for (int m = 0; m < 64; m += 4) {
            float4 w = *(const float4*)&sW2t[k * 64 + m];
            hv0 = fmaf(h1[m],   w.x, hv0); hv1 = fmaf(h1[m+1], w.y, hv1);
            hv2 = fmaf(h1[m+2], w.z, hv2); hv3 = fmaf(h1[m+3], w.w, hv3);
        }
        float hv = fmaxf(hv0 + hv1 + hv2 + hv3, 0.f);
#pragma unroll
        for (int j = 0; j < 64; j += 4) {
            float4 w = *(const float4*)&sW3[k * 64 + j];
            acc[j]   = fmaf(hv, w.x, acc[j]);   acc[j+1] = fmaf(hv, w.y, acc[j+1]);
            acc[j+2] = fmaf(hv, w.z, acc[j+2]); acc[j+3] = fmaf(hv, w.w, acc[j+3]);
        }
    }
#pragma unroll
    for (int j = 0; j < 64; j += 4)
        *(float4*)&g_h[n * 64 + j] = make_float4(acc[j], acc[j+1], acc[j+2], acc[j+3]);
}

// ---------------------------------------------------------------------------
// Kernel 2: segment starts from sorted batch_hyper
// ---------------------------------------------------------------------------
__global__ void k_seg(const int* __restrict__ bh, int E, int G)
{
    int e = blockIdx.x * blockDim.x + threadIdx.x;
    if (e >= E) return;
    int cur = bh[e];
    if (e == 0) { for (int g = 0; g <= cur; g++) g_seg[g] = 0; }
    else { int prev = bh[e - 1]; for (int g = prev + 1; g <= cur; g++) g_seg[g] = e; }
    if (e == E - 1) { for (int g = cur + 1; g <= G; g++) g_seg[g] = E; }
}

// ---------------------------------------------------------------------------
// Kernel 3: per-(graph, feature) softmax stats: t = max + log(sum exp)
// ---------------------------------------------------------------------------
__global__ __launch_bounds__(256)
void k_stats(const int* __restrict__ hei, int E, int R)
{
    int g = blockIdx.x;
    int s0 = g_seg[g], s1 = g_seg[g + 1];
    int f = threadIdx.x & 63, sub = threadIdx.x >> 6;

    float m = -FLT_MAX, s = 0.f;
    for (int e = s0 + sub; e < s1; e += 4) {
        float xh = 0.f;
        for (int ri = 0; ri < R; ri++) {
            int idx = hei[ri * E + e];
            xh += g_h[idx * 64 + f];
        }
        if (xh > m) { s = s * __expf(m - xh) + 1.f; m = xh; }
        else        { s += __expf(xh - m); }
    }
    __shared__ float sm[4][64], ss[4][64];
    sm[sub][f] = m; ss[sub][f] = s;
    __syncthreads();
    if (sub == 0) {
        float M = sm[0][f];
#pragma unroll
        for (int k = 1; k < 4; k++) M = fmaxf(M, sm[k][f]);
        float S = 0.f;
#pragma unroll
        for (int k = 0; k < 4; k++) S += ss[k][f] * __expf(sm[k][f] - M);
        g_t[g * 64 + f] = M + __logf(S);
    }
}

// ---------------------------------------------------------------------------
// Kernel 4: persistent fused edge pipeline on mma.sync tf32 (HMMA).
// 128 edges/tile, 256 threads (8 warps: 4 m-quarters x 2 n-halves).
// Activations [edge][feat] stride 68; weights [k][n] stride 72 (tf32).
// ---------------------------------------------------------------------------
#define SA 68
#define SW 72
// SMEM float offsets
#define O_X   0                       // 128*68
#define O_H   8704
#define O_T   17408                   // t-rows, later mid
#define O_W   26112                   // 64*72
#define O_V1  30720                   // 128*72
#define O_V2  39936                   // 64*72
#define O_V3  44544
#define O_C1  44608
#define O_C2  44672
#define O_P   44736                   // 2*128 partials
#define O_G   44992                   // 128 ints
#define SMEM_FLOATS 45120             // 180480 B

__device__ __forceinline__ void pass64(const float* __restrict__ A,
                                       const float* __restrict__ Bw,
                                       int mq, int nh, int lane,
                                       float acc[2][4][4])
{
    int kr = lane & 3, rg = lane >> 2;
    uint32_t Bf[8][4][2];
#pragma unroll
    for (int k = 0; k < 8; k++)
#pragma unroll
        for (int nt = 0; nt < 4; nt++) {
            const float* bp = Bw + (k * 8 + kr) * SW + nh * 32 + nt * 8 + rg;
            Bf[k][nt][0] = __float_as_uint(bp[0]);
            Bf[k][nt][1] = __float_as_uint(bp[4 * SW]);
        }
#pragma unroll
    for (int mt = 0; mt < 2; mt++) {
        const float* ap = A + (mq * 32 + mt * 16 + rg) * SA + kr;
#pragma unroll
        for (int k = 0; k < 8; k++) {
            uint32_t a0 = __float_as_uint(ap[k * 8]);
            uint32_t a1 = __float_as_uint(ap[k * 8 + 8 * SA]);
            uint32_t a2 = __float_as_uint(ap[k * 8 + 4]);
            uint32_t a3 = __float_as_uint(ap[k * 8 + 8 * SA + 4]);
#pragma unroll
            for (int nt = 0; nt < 4; nt++)
                mma8(acc[mt][nt], a0, a1, a2, a3, Bf[k][nt][0], Bf[k][nt][1]);
        }
    }
}

__global__ __launch_bounds__(256)
void k_fused_tc(const int* __restrict__ hei, const int* __restrict__ bh,
                int E, int R, int ntiles,
                const float* __restrict__ Wt,
                const float* __restrict__ V1, const float* __restrict__ c1,
                const float* __restrict__ V2, const float* __restrict__ c2,
                const float* __restrict__ V3, const float* __restrict__ c3,
                float* __restrict__ out, int write_bh)
{
    extern __shared__ float smf[];
    float* X  = smf + O_X;
    float* H  = smf + O_H;
    float* Tm = smf + O_T;
    float* Wb  = smf + O_W;
    float* V1b = smf + O_V1;
    float* V2b = smf + O_V2;
    float* sV3 = smf + O_V3;
    float* sc1 = smf + O_C1;
    float* sc2 = smf + O_C2;
    float* P   = smf + O_P;
    int*   sG  = (int*)(smf + O_G);

    int tid = threadIdx.x, lane = tid & 31, wid = tid >> 5;
    int mq = wid >> 1, nh = wid & 1;
    int kr = lane & 3, rg = lane >> 2;

    // ---- one-time weight staging (tf32 RNA) ----
    for (int i = tid; i < 64 * 64; i += 256) {
        int k = i >> 6, n = i & 63;
        Wb[k * SW + n]  = tf32r(Wt[i]);
        V2b[k * SW + n] = tf32r(V2[i]);
    }
    for (int i = tid; i < 128 * 64; i += 256) {
        int k = i >> 6, n = i & 63;
        V1b[k * SW + n] = tf32r(V1[i]);
    }
    if (tid < 64) { sV3[tid] = V3[tid]; sc1[tid] = c1[tid]; sc2[tid] = c2[tid]; }
    float c3v = c3[0];
    __syncthreads();

    int el = tid & 127, half = tid >> 7, f0 = half * 32;

    for (int tile = blockIdx.x; tile < ntiles; tile += gridDim.x) {
        int base = tile * 128;
        int e = base + el; if (e >= E) e = E - 1;
        int g = bh[e];
        if (half == 0) sG[el] = g;

        // ---- gather x_hyper (full fp32) + stage t rows ----
        {
            float xa[32];
#pragma unroll
            for (int q = 0; q < 32; q++) xa[q] = 0.f;
            for (int ri = 0; ri < R; ri++) {
                const float4* hp = (const float4*)&g_h[hei[ri * E + e] * 64 + f0];
#pragma unroll
                for (int q = 0; q < 8; q++) {
                    float4 v = hp[q];
                    xa[q*4+0] += v.x; xa[q*4+1] += v.y;
                    xa[q*4+2] += v.z; xa[q*4+3] += v.w;
                }
            }
            float* xd = &X[el * SA + f0];
#pragma unroll
            for (int q = 0; q < 16; q++)
                *(float2*)&xd[2 * q] = make_float2(xa[2*q], xa[2*q+1]);
            const float2* tp = (const float2*)&g_t[g * 64 + f0];
            float* td = &Tm[el * SA + f0];
#pragma unroll
            for (int q = 0; q < 16; q++)
                *(float2*)&td[2 * q] = tp[q];
        }
        __syncthreads();

        float acc[2][4][4];

        // ---- GEMM 1: x_hyper @ weight ----
#pragma unroll
        for (int a = 0; a < 2; a++)
#pragma unroll
            for (int b = 0; b < 4; b++)
#pragma unroll
                for (int c = 0; c < 4; c++) acc[a][b][c] = 0.f;
        pass64(X, Wb, mq, nh, lane, acc);

        // epi1: H = tf32( relu(d) * exp(x - t) )
#pragma unroll
        for (int mt = 0; mt < 2; mt++) {
            int r0 = (mq * 32 + mt * 16 + rg) * SA;
            int r1 = r0 + 8 * SA;
#pragma unroll
            for (int nt = 0; nt < 4; nt++) {
                int j = nh * 32 + nt * 8 + 2 * kr;
                float2 x0 = *(float2*)&X[r0 + j], t0 = *(float2*)&Tm[r0 + j];
                float2 x1 = *(float2*)&X[r1 + j], t1 = *(float2*)&Tm[r1 + j];
                float h00 = fmaxf(acc[mt][nt][0], 0.f) * __expf(x0.x - t0.x);
                float h01 = fmaxf(acc[mt][nt][1], 0.f) * __expf(x0.y - t0.y);
                float h10 = fmaxf(acc[mt][nt][2], 0.f) * __expf(x1.x - t1.x);
                float h11 = fmaxf(acc[mt][nt][3], 0.f) * __expf(x1.y - t1.y);
                *(float2*)&H[r0 + j] = make_float2(tf32r(h00), tf32r(h01));
                *(float2*)&H[r1 + j] = make_float2(tf32r(h10), tf32r(h11));
            }
        }
        __syncthreads();

        // ---- GEMM 2: [x || x_hat] @ V1 (K = 128) ----
#pragma unroll
        for (int a = 0; a < 2; a++)
#pragma unroll
            for (int b = 0; b < 4; b++)
#pragma unroll
                for (int c = 0; c < 4; c++) acc[a][b][c] = 0.f;
        pass64(X, V1b,            mq, nh, lane, acc);
        pass64(H, V1b + 64 * SW,  mq, nh, lane, acc);

        // epi2: mid = tf32(relu(d + c1)) -> Tm
#pragma unroll
        for (int mt = 0; mt < 2; mt++) {
            int r0 = (mq * 32 + mt * 16 + rg) * SA;
            int r1 = r0 + 8 * SA;
#pragma unroll
            for (int nt = 0; nt < 4; nt++) {
                int j = nh * 32 + nt * 8 + 2 * kr;
                float b0 = sc1[j], b1 = sc1[j + 1];
                *(float2*)&Tm[r0 + j] = make_float2(tf32r(fmaxf(acc[mt][nt][0] + b0, 0.f)),
                                                    tf32r(fmaxf(acc[mt][nt][1] + b1, 0.f)));
                *(float2*)&Tm[r1 + j] = make_float2(tf32r(fmaxf(acc[mt][nt][2] + b0, 0.f)),
                                                    tf32r(fmaxf(acc[mt][nt][3] + b1, 0.f)));
            }
        }
        __syncthreads();

        // ---- GEMM 3: mid @ V2 ----
#pragma unroll
        for (int a = 0; a < 2; a++)
#pragma unroll
            for (int b = 0; b < 4; b++)
#pragma unroll
                for (int c = 0; c < 4; c++) acc[a][b][c] = 0.f;
        pass64(Tm, V2b, mq, nh, lane, acc);

        // epi3: partial dot with V3 after relu(+c2), reduce over lane%4
#pragma unroll
        for (int mt = 0; mt < 2; mt++) {
            float s0 = 0.f, s1 = 0.f;
#pragma unroll
            for (int nt = 0; nt < 4; nt++) {
                int j = nh * 32 + nt * 8 + 2 * kr;
                float b0 = sc2[j], b1 = sc2[j + 1];
                float w0 = sV3[j], w1 = sV3[j + 1];
                s0 = fmaf(fmaxf(acc[mt][nt][0] + b0, 0.f), w0, s0);
                s0 = fmaf(fmaxf(acc[mt][nt][1] + b1, 0.f), w1, s0);
                s1 = fmaf(fmaxf(acc[mt][nt][2] + b0, 0.f), w0, s1);
                s1 = fmaf(fmaxf(acc[mt][nt][3] + b1, 0.f), w1, s1);
            }
            s0 += __shfl_xor_sync(0xFFFFFFFF, s0, 1);
            s0 += __shfl_xor_sync(0xFFFFFFFF, s0, 2);
            s1 += __shfl_xor_sync(0xFFFFFFFF, s1, 1);
            s1 += __shfl_xor_sync(0xFFFFFFFF, s1, 2);
            if (kr == 0) {
                int r = mq * 32 + mt * 16 + rg;
                P[nh * 128 + r]     = s0;
                P[nh * 128 + r + 8] = s1;
            }
        }
        __syncthreads();

        if (tid < 128) {
            int eo = base + tid;
            float v = P[tid] + P[128 + tid] + c3v;
            float o = 1.f / (1.f + __expf(-v));
            if (eo < E) {
                out[eo] = o;
                if (write_bh) out[E + eo] = (float)sG[tid];
            }
        }
        __syncthreads();
    }
}

// ---------------------------------------------------------------------------
extern "C" void kernel_launch(void* const* d_in, const int* in_sizes, int n_in,
                              void* d_out, int out_size)
{
    const float* x     = (const float*)d_in[0];
    const float* u     = (const float*)d_in[1];
    const int*   batch = (const int*)d_in[2];
    const int*   hei   = (const int*)d_in[3];
    const int*   bh    = (const int*)d_in[4];

    int N = in_sizes[2];
    int E = in_sizes[4];
    int G = in_sizes[1] / 4;
    int R = in_sizes[3] / E;

    int wb = 5;
    while (wb < n_in && in_sizes[wb] != 640) wb++;
    const float* W1 = (const float*)d_in[wb + 0];
    const float* b1 = (const float*)d_in[wb + 1];
    const float* W2 = (const float*)d_in[wb + 2];
    const float* b2 = (const float*)d_in[wb + 3];
    const float* W3 = (const float*)d_in[wb + 4];
    const float* b3 = (const float*)d_in[wb + 5];
    const float* Wt = (const float*)d_in[wb + 6];
    const float* V1 = (const float*)d_in[wb + 7];
    const float* c1 = (const float*)d_in[wb + 8];
    const float* V2 = (const float*)d_in[wb + 9];
    const float* c2 = (const float*)d_in[wb + 10];
    const float* V3 = (const float*)d_in[wb + 11];
    const float* c3 = (const float*)d_in[wb + 12];

    float* out = (float*)d_out;
    int write_bh = (out_size >= 2 * E) ? 1 : 0;

    k_node_mlp<<<(N + 127) / 128, 128>>>(x, u, batch, N, W1, b1, W2, b2, W3, b3);
    k_seg<<<(E + 255) / 256, 256>>>(bh, E, G);
    k_stats<<<G, 256>>>(hei, E, R);

    int ntiles = (E + 127) / 128;
    int dev = 0, nsm = 148;
    cudaGetDevice(&dev);
    cudaDeviceGetAttribute(&nsm, cudaDevAttrMultiProcessorCount, dev);
    int grid = (ntiles < nsm) ? ntiles : nsm;

    size_t shbytes = (size_t)SMEM_FLOATS * sizeof(float);   // ~180.5 KB
    cudaFuncSetAttribute(k_fused_tc, cudaFuncAttributeMaxDynamicSharedMemorySize, (int)shbytes);
    k_fused_tc<<<grid, 256, shbytes>>>(hei, bh, E, R, ntiles, Wt, V1, c1, V2, c2,
                                       V3, c3, out, write_bh);
}

// round 5
// speedup vs baseline: 2.1644x; 1.0023x over previous
#include <cuda_runtime.h>
#include <float.h>
#include <stdint.h>

#define MAXN 32768
#define MAXG 2048

// Scratch (no allocations allowed -> __device__ globals)
__device__ float g_h[MAXN * 64];     // node embeddings (8 MB, L2-resident)
__device__ float g_t[MAXG * 64];     // per (graph, feature): max + log(sum exp)
__device__ int   g_seg[MAXG + 1];    // segment starts in sorted batch_hyper

static __device__ __forceinline__ float tf32r(float x) {
    uint32_t r; asm("cvt.rna.tf32.f32 %0, %1;" : "=r"(r) : "f"(x));
    return __uint_as_float(r);
}
static __device__ __forceinline__ void mma8(float c[4], uint32_t a0, uint32_t a1,
                                            uint32_t a2, uint32_t a3,
                                            uint32_t b0, uint32_t b1) {
    asm volatile("mma.sync.aligned.m16n8k8.row.col.f32.tf32.tf32.f32 "
                 "{%0,%1,%2,%3}, {%4,%5,%6,%7}, {%8,%9}, {%0,%1,%2,%3};"
                 : "+f"(c[0]), "+f"(c[1]), "+f"(c[2]), "+f"(c[3])
                 : "r"(a0), "r"(a1), "r"(a2), "r"(a3), "r"(b0), "r"(b1));
}
static __device__ __forceinline__ void gbar(int id) {
    asm volatile("bar.sync %0, %1;" :: "r"(id), "r"(128) : "memory");
}

// ---------------------------------------------------------------------------
// Kernel 1: node MLP
// ---------------------------------------------------------------------------
__global__ __launch_bounds__(128)
void k_node_mlp(const float* __restrict__ x, const float* __restrict__ u,
                const int* __restrict__ batch, int N,
                const float* __restrict__ W1, const float* __restrict__ b1,
                const float* __restrict__ W2, const float* __restrict__ b2,
                const float* __restrict__ W3, const float* __restrict__ b3)
{
    __shared__ float sW1[640], sW2t[4096], sW3[4096], sb1[64], sb2[64], sb3[64];
    int tid = threadIdx.x;
    for (int i = tid; i < 640; i += 128) sW1[i] = W1[i];
    for (int i = tid; i < 4096; i += 128) {
        int m = i >> 6, k = i & 63;
        sW2t[k * 64 + m] = W2[i];
        sW3[i] = W3[i];
    }
    if (tid < 64) { sb1[tid] = b1[tid]; sb2[tid] = b2[tid]; sb3[tid] = b3[tid]; }
    __syncthreads();

    int n = blockIdx.x * 128 + tid;
    if (n >= N) return;

    float in[10];
#pragma unroll
    for (int k = 0; k < 6; k++) in[k] = x[n * 6 + k];
    int g = batch[n];
#pragma unroll
    for (int k = 0; k < 4; k++) in[6 + k] = u[g * 4 + k];

    float h1[64];
#pragma unroll
    for (int j = 0; j < 64; j++) h1[j] = sb1[j];
#pragma unroll
    for (int k = 0; k < 10; k++) {
        float v = in[k];
#pragma unroll
        for (int j = 0; j < 64; j += 4) {
            float4 w = *(const float4*)&sW1[k * 64 + j];
            h1[j]   = fmaf(v, w.x, h1[j]);   h1[j+1] = fmaf(v, w.y, h1[j+1]);
            h1[j+2] = fmaf(v, w.z, h1[j+2]); h1[j+3] = fmaf(v, w.w, h1[j+3]);
        }
    }
#pragma unroll
    for (int j = 0; j < 64; j++) h1[j] = fmaxf(h1[j], 0.f);

    float acc[64];
#pragma unroll
    for (int j = 0; j < 64; j++) acc[j] = sb3[j];
    for (int k = 0; k < 64; k++) {
        float hv0 = sb2[k], hv1 = 0.f, hv2 = 0.f, hv3 = 0.f;
#pragma unroll
        for (int m = 0; m < 64; m += 4) {
            float4 w = *(const float4*)&sW2t[k * 64 + m];
            hv0 = fmaf(h1[m],   w.x, hv0); hv1 = fmaf(h1[m+1], w.y, hv1);
            hv2 = fmaf(h1[m+2], w.z, hv2); hv3 = fmaf(h1[m+3], w.w, hv3);
        }
        float hv = fmaxf(hv0 + hv1 + hv2 + hv3, 0.f);
#pragma unroll
        for (int j = 0; j < 64; j += 4) {
            float4 w = *(const float4*)&sW3[k * 64 + j];
            acc[j]   = fmaf(hv, w.x, acc[j]);   acc[j+1] = fmaf(hv, w.y, acc[j+1]);
            acc[j+2] = fmaf(hv, w.z, acc[j+2]); acc[j+3] = fmaf(hv, w.w, acc[j+3]);
        }
    }
#pragma unroll
    for (int j = 0; j < 64; j += 4)
        *(float4*)&g_h[n * 64 + j] = make_float4(acc[j], acc[j+1], acc[j+2], acc[j+3]);
}

// ---------------------------------------------------------------------------
// Kernel 2: segment starts from sorted batch_hyper
// ---------------------------------------------------------------------------
__global__ void k_seg(const int* __restrict__ bh, int E, int G)
{
    int e = blockIdx.x * blockDim.x + threadIdx.x;
    if (e >= E) return;
    int cur = bh[e];
    if (e == 0) { for (int g = 0; g <= cur; g++) g_seg[g] = 0; }
    else { int prev = bh[e - 1]; for (int g = prev + 1; g <= cur; g++) g_seg[g] = e; }
    if (e == E - 1) { for (int g = cur + 1; g <= G; g++) g_seg[g] = E; }
}

// ---------------------------------------------------------------------------
// Kernel 3: per-(graph, feature) softmax stats: t = max + log(sum exp)
// ---------------------------------------------------------------------------
__global__ __launch_bounds__(256)
void k_stats(const int* __restrict__ hei, int E, int R)
{
    int g = blockIdx.x;
    int s0 = g_seg[g], s1 = g_seg[g + 1];
    int f = threadIdx.x & 63, sub = threadIdx.x >> 6;

    float m = -FLT_MAX, s = 0.f;
    for (int e = s0 + sub; e < s1; e += 4) {
        float xh = 0.f;
        for (int ri = 0; ri < R; ri++) {
            int idx = hei[ri * E + e];
            xh += g_h[idx * 64 + f];
        }
        if (xh > m) { s = s * __expf(m - xh) + 1.f; m = xh; }
        else        { s += __expf(xh - m); }
    }
    __shared__ float sm[4][64], ss[4][64];
    sm[sub][f] = m; ss[sub][f] = s;
    __syncthreads();
    if (sub == 0) {
        float M = sm[0][f];
#pragma unroll
        for (int k = 1; k < 4; k++) M = fmaxf(M, sm[k][f]);
        float S = 0.f;
#pragma unroll
        for (int k = 0; k < 4; k++) S += ss[k][f] * __expf(sm[k][f] - M);
        g_t[g * 64 + f] = M + __logf(S);
    }
}

// ---------------------------------------------------------------------------
// Kernel 4: persistent fused edge pipeline, mma.sync tf32.
// 256 threads = TWO independent 4-warp groups, each on its own 128-edge tile
// with its own named barrier + staging buffers (latency overlap).
// Weights pre-packed in B-fragment order (LDS.128 loads).
// ---------------------------------------------------------------------------
#define SA 68
// SMEM float offsets
#define O_WPK  0            // 4096
#define O_V1PK 4096         // 8192 (two 64-K halves)
#define O_V2PK 12288        // 4096
#define O_X    16384        // 2 x 8704
#define O_H    33792        // 2 x 8704
#define O_V3   51200
#define O_C1   51264
#define O_C2   51328
#define O_G    51392        // 2 x 128 ints
#define SMEM_FLOATS 51648   // 206,592 B

// One K=64 slab: A row-major [128][SA], Bpk fragment-packed. Warp covers
// rows mq*32..mq*32+31, all 64 cols. acc[2][8][4].
__device__ __forceinline__ void pass64(const float* __restrict__ A,
                                       const float* __restrict__ Bpk,
                                       int mq, int lane, float acc[2][8][4])
{
    int kr = lane & 3, rg = lane >> 2;
#pragma unroll
    for (int s = 0; s < 8; s++) {
        float bq[16];
#pragma unroll
        for (int q = 0; q < 4; q++)
            *(float4*)&bq[q * 4] = *(const float4*)&Bpk[s * 512 + q * 128 + lane * 4];
#pragma unroll
        for (int mt = 0; mt < 2; mt++) {
            const float* ap = A + (mq * 32 + mt * 16 + rg) * SA + kr + s * 8;
            uint32_t a0 = __float_as_uint(ap[0]);
            uint32_t a1 = __float_as_uint(ap[8 * SA]);
            uint32_t a2 = __float_as_uint(ap[4]);
            uint32_t a3 = __float_as_uint(ap[8 * SA + 4]);
#pragma unroll
            for (int nt = 0; nt < 8; nt++)
                mma8(acc[mt][nt], a0, a1, a2, a3,
                     __float_as_uint(bq[2 * nt]), __float_as_uint(bq[2 * nt + 1]));
        }
    }
}

// Pack a 64x64 (k x n, row-major) block into B-fragment order (tf32).
__device__ __forceinline__ void packW(float* __restrict__ dst,
                                      const float* __restrict__ src, int tid)
{
    for (int i = tid; i < 4096; i += 256) {
        int s = i >> 9, r = i & 511;
        int q = r >> 7, r2 = r & 127;
        int l = r2 >> 2, c = r2 & 3;
        int kk = s * 8 + (l & 3) + (c & 1) * 4;
        int nn = (q * 2 + (c >> 1)) * 8 + (l >> 2);
        dst[i] = tf32r(src[kk * 64 + nn]);
    }
}

__global__ __launch_bounds__(256, 1)
void k_fused_tc(const int* __restrict__ hei, const int* __restrict__ bh,
                int E, int R, int ntiles,
                const float* __restrict__ Wt,
                const float* __restrict__ V1, const float* __restrict__ c1,
                const float* __restrict__ V2, const float* __restrict__ c2,
                const float* __restrict__ V3, const float* __restrict__ c3,
                float* __restrict__ out, int write_bh)
{
    extern __shared__ float smf[];
    float* sV3 = smf + O_V3;
    float* sc1 = smf + O_C1;
    float* sc2 = smf + O_C2;

    int tid = threadIdx.x, lane = tid & 31, wid = tid >> 5;
    int gi = wid >> 2;                 // group 0 or 1
    int mq = wid & 3;                  // warp's m-quarter within group
    int kr = lane & 3, rg = lane >> 2;
    int bar = gi + 1;
    int gt = tid & 127;                // thread id within group

    float* X = smf + O_X + gi * 8704;
    float* H = smf + O_H + gi * 8704;
    int*   sG = (int*)(smf + O_G) + gi * 128;

    // ---- one-time weight packing ----
    packW(smf + O_WPK,        Wt,            tid);
    packW(smf + O_V1PK,       V1,            tid);
    packW(smf + O_V1PK + 4096, V1 + 64 * 64, tid);
    packW(smf + O_V2PK,       V2,            tid);
    if (tid < 64) { sV3[tid] = V3[tid]; sc1[tid] = c1[tid]; sc2[tid] = c2[tid]; }
    float c3v = c3[0];
    __syncthreads();

    for (int tile = blockIdx.x * 2 + gi; tile < ntiles; tile += gridDim.x * 2) {
        int base = tile * 128;

        // ---- gather: one edge per thread, 64 feats; stage t-row into H ----
        {
            int e = base + gt; if (e >= E) e = E - 1;
            int g = bh[e];
            sG[gt] = g;
            float xa[64];
            {
                const float4* hp = (const float4*)&g_h[hei[e] * 64];
#pragma unroll
                for (int q = 0; q < 16; q++) {
                    float4 v = hp[q];
                    xa[q*4+0] = v.x; xa[q*4+1] = v.y; xa[q*4+2] = v.z; xa[q*4+3] = v.w;
                }
            }
            for (int ri = 1; ri < R; ri++) {
                const float4* hp = (const float4*)&g_h[hei[ri * E + e] * 64];
#pragma unroll
                for (int q = 0; q < 16; q++) {
                    float4 v = hp[q];
                    xa[q*4+0] += v.x; xa[q*4+1] += v.y; xa[q*4+2] += v.z; xa[q*4+3] += v.w;
                }
            }
            float* xd = &X[gt * SA];
#pragma unroll
            for (int q = 0; q < 16; q++)
                *(float4*)&xd[q * 4] = make_float4(xa[q*4], xa[q*4+1], xa[q*4+2], xa[q*4+3]);
            const float4* tp = (const float4*)&g_t[g * 64];
            float* td = &H[gt * SA];
#pragma unroll
            for (int q = 0; q < 16; q++)
                *(float4*)&td[q * 4] = tp[q];
        }
        gbar(bar);

        float acc[2][8][4];

        // ---- GEMM 1: x_hyper @ weight ----
#pragma unroll
        for (int a = 0; a < 2; a++)
#pragma unroll
            for (int b = 0; b < 8; b++)
#pragma unroll
                for (int c = 0; c < 4; c++) acc[a][b][c] = 0.f;
        pass64(X, smf + O_WPK, mq, lane, acc);

        // epi1: H = relu(d) * exp(x - t)   (t pre-staged in H, same positions)
#pragma unroll
        for (int mt = 0; mt < 2; mt++) {
            int r0 = (mq * 32 + mt * 16 + rg) * SA;
            int r1 = r0 + 8 * SA;
#pragma unroll
            for (int nt = 0; nt < 8; nt++) {
                int j = nt * 8 + 2 * kr;
                float2 x0 = *(float2*)&X[r0 + j], t0 = *(float2*)&H[r0 + j];
                float2 x1 = *(float2*)&X[r1 + j], t1 = *(float2*)&H[r1 + j];
                float h00 = fmaxf(acc[mt][nt][0], 0.f) * __expf(x0.x - t0.x);
                float h01 = fmaxf(acc[mt][nt][1], 0.f) * __expf(x0.y - t0.y);
                float h10 = fmaxf(acc[mt][nt][2], 0.f) * __expf(x1.x - t1.x);
                float h11 = fmaxf(acc[mt][nt][3], 0.f) * __expf(x1.y - t1.y);
                *(float2*)&H[r0 + j] = make_float2(h00, h01);
                *(float2*)&H[r1 + j] = make_float2(h10, h11);
            }
        }
        gbar(bar);

        // ---- GEMM 2: [x || x_hat] @ V1  (K = 128) ----
#pragma unroll
        for (int a = 0; a < 2; a++)
#pragma unroll
            for (int b = 0; b < 8; b++)
#pragma unroll
                for (int c = 0; c < 4; c++) acc[a][b][c] = 0.f;
        pass64(X, smf + O_V1PK,        mq, lane, acc);
        pass64(H, smf + O_V1PK + 4096, mq, lane, acc);
        gbar(bar);   // all GEMM2 reads of X/H done

        // epi2: mid = relu(d + c1) -> H
#pragma unroll
        for (int mt = 0; mt < 2; mt++) {
            int r0 = (mq * 32 + mt * 16 + rg) * SA;
            int r1 = r0 + 8 * SA;
#pragma unroll
            for (int nt = 0; nt < 8; nt++) {
                int j = nt * 8 + 2 * kr;
                float b0 = sc1[j], b1 = sc1[j + 1];
                *(float2*)&H[r0 + j] = make_float2(fmaxf(acc[mt][nt][0] + b0, 0.f),
                                                   fmaxf(acc[mt][nt][1] + b1, 0.f));
                *(float2*)&H[r1 + j] = make_float2(fmaxf(acc[mt][nt][2] + b0, 0.f),
                                                   fmaxf(acc[mt][nt][3] + b1, 0.f));
            }
        }
        gbar(bar);

        // ---- GEMM 3: mid @ V2 ----
#pragma unroll
        for (int a = 0; a < 2; a++)
#pragma unroll
            for (int b = 0; b < 8; b++)
#pragma unroll
                for (int c = 0; c < 4; c++) acc[a][b][c] = 0.f;
        pass64(H, smf + O_V2PK, mq, lane, acc);

        // epi3: relu(+c2), dot V3 over this thread's 16 cols, reduce over kr
#pragma unroll
        for (int mt = 0; mt < 2; mt++) {
            float s0 = 0.f, s1 = 0.f;
#pragma unroll
            for (int nt = 0; nt < 8; nt++) {
                int j = nt * 8 + 2 * kr;
                float b0 = sc2[j], b1 = sc2[j + 1];
                float w0 = sV3[j], w1 = sV3[j + 1];
                s0 = fmaf(fmaxf(acc[mt][nt][0] + b0, 0.f), w0, s0);
                s0 = fmaf(fmaxf(acc[mt][nt][1] + b1, 0.f), w1, s0);
                s1 = fmaf(fmaxf(acc[mt][nt][2] + b0, 0.f), w0, s1);
                s1 = fmaf(fmaxf(acc[mt][nt][3] + b1, 0.f), w1, s1);
            }
            s0 += __shfl_xor_sync(0xFFFFFFFF, s0, 1);
            s0 += __shfl_xor_sync(0xFFFFFFFF, s0, 2);
            s1 += __shfl_xor_sync(0xFFFFFFFF, s1, 1);
            s1 += __shfl_xor_sync(0xFFFFFFFF, s1, 2);
            if (kr == 0) {
                int r0 = mq * 32 + mt * 16 + rg;
                int e0 = base + r0, e1 = e0 + 8;
                float o0 = 1.f / (1.f + __expf(-s0));
                float o1 = 1.f / (1.f + __expf(-s1));
                if (e0 < E) {
                    out[e0] = o0;
                    if (write_bh) out[E + e0] = (float)sG[r0];
                }
                if (e1 < E) {
                    out[e1] = o1;
                    if (write_bh) out[E + e1] = (float)sG[r0 + 8];
                }
            }
        }
        gbar(bar);   // protect X/H from next tile's gather
    }
}

// ---------------------------------------------------------------------------
extern "C" void kernel_launch(void* const* d_in, const int* in_sizes, int n_in,
                              void* d_out, int out_size)
{
    const float* x     = (const float*)d_in[0];
    const float* u     = (const float*)d_in[1];
    const int*   batch = (const int*)d_in[2];
    const int*   hei   = (const int*)d_in[3];
    const int*   bh    = (const int*)d_in[4];

    int N = in_sizes[2];
    int E = in_sizes[4];
    int G = in_sizes[1] / 4;
    int R = in_sizes[3] / E;

    int wb = 5;
    while (wb < n_in && in_sizes[wb] != 640) wb++;
    const float* W1 = (const float*)d_in[wb + 0];
    const float* b1 = (const float*)d_in[wb + 1];
    const float* W2 = (const float*)d_in[wb + 2];
    const float* b2 = (const float*)d_in[wb + 3];
    const float* W3 = (const float*)d_in[wb + 4];
    const float* b3 = (const float*)d_in[wb + 5];
    const float* Wt = (const float*)d_in[wb + 6];
    const float* V1 = (const float*)d_in[wb + 7];
    const float* c1 = (const float*)d_in[wb + 8];
    const float* V2 = (const float*)d_in[wb + 9];
    const float* c2 = (const float*)d_in[wb + 10];
    const float* V3 = (const float*)d_in[wb + 11];
    const float* c3 = (const float*)d_in[wb + 12];

    float* out = (float*)d_out;
    int write_bh = (out_size >= 2 * E) ? 1 : 0;

    k_node_mlp<<<(N + 127) / 128, 128>>>(x, u, batch, N, W1, b1, W2, b2, W3, b3);
    k_seg<<<(E + 255) / 256, 256>>>(bh, E, G);
    k_stats<<<G, 256>>>(hei, E, R);

    int ntiles = (E + 127) / 128;
    int dev = 0, nsm = 148;
    cudaGetDevice(&dev);
    cudaDeviceGetAttribute(&nsm, cudaDevAttrMultiProcessorCount, dev);
    int grid = (ntiles + 1) / 2;
    if (grid > nsm) grid = nsm;
    if (grid < 1) grid = 1;

    size_t shbytes = (size_t)SMEM_FLOATS * sizeof(float);   // ~206.6 KB
    cudaFuncSetAttribute(k_fused_tc, cudaFuncAttributeMaxDynamicSharedMemorySize, (int)shbytes);
    k_fused_tc<<<grid, 256, shbytes>>>(hei, bh, E, R, ntiles, Wt, V1, c1, V2, c2,
                                       V3, c3, out, write_bh);
}